// round 13
// baseline (speedup 1.0000x reference)
#include <cuda_runtime.h>
#include <math.h>

// Kalman filter B=2048, T=64, STATE=32, OBS=16.
// SPECIAL PATH (F=I, Q=qI, R=rI, cov0=I — verified per CTA):
//   fused_kernel: per-CTA Gram-matrix Jacobi eigendecomp of HH^T (noise-level
//   early exit, fast-math rotation chain, split row phase) + scalar gain
//   recursions, then 16 warps each filter one batch.
// FALLBACK: verified phase1/phase2 (phase1 publishes g_special).

#define SD 32
#define OD 16
#define TT 64
#define NB 2048
#define P32 33
#define P16 17

#define BAR1() asm volatile("bar.sync 1, 256;" ::: "memory")

__device__ int g_special;
__device__ __align__(16) float g_W[TT][48 * SD];
__device__ int g_tconv;

// ---------------------------------------------------------------------------
// Fused special-path kernel
// ---------------------------------------------------------------------------
__global__ void __launch_bounds__(512, 1) fused_kernel(
    const float* __restrict__ x0g,
    const float* __restrict__ meas,   // (B, T, 16)
    float* __restrict__ out,          // (B, T, 32)
    const float* __restrict__ Fg, const float* __restrict__ Hg,
    const float* __restrict__ Qg, const float* __restrict__ Rg,
    const float* __restrict__ cov0)
{
    extern __shared__ float4 zb_dyn[];      // [16][256] float4 = 64KB

    __shared__ float Hs[OD * 33];           // H rows (kept for V recovery)
    __shared__ float Ms[OD * 17];           // Gram matrix H H^T
    __shared__ float Wacc[OD * 17];         // accumulated rotations = U^T
    __shared__ float sig[OD];
    __shared__ float2 ab2[TT * OD];         // (a_i,t , k_i,t)
    __shared__ float Us[OD * OD];
    __shared__ float Vs[SD * 17];
    __shared__ float thr2s;
    __shared__ int notconv;

    const int tid  = threadIdx.x;
    const int w    = tid >> 5;
    const int lane = tid & 31;
    const int i16  = lane & 15;
    const float q = Qg[0], r = Rg[0];

    // ---- issue batch loads EARLY ----
    const int b = blockIdx.x * 16 + w;
    const float4* zg = (const float4*)(meas + (size_t)b * TT * OD);
    float4 zr0 = zg[0 * 32 + lane];
    float4 zr1 = zg[1 * 32 + lane];
    float4 zr2 = zg[2 * 32 + lane];
    float4 zr3 = zg[3 * 32 + lane];
    float4 zr4 = zg[4 * 32 + lane];
    float4 zr5 = zg[5 * 32 + lane];
    float4 zr6 = zg[6 * 32 + lane];
    float4 zr7 = zg[7 * 32 + lane];
    float x0reg = x0g[b * SD + lane];

    // ---- specialness check (all 512 threads) ----
    {
        bool ok = (r > 0.f) && (q >= 0.f);
        #pragma unroll
        for (int s = 0; s < 2; s++) {
            int e = tid + s * 512;
            int i = e >> 5, j = e & 31;
            float ide = (i == j) ? 1.f : 0.f;
            if (Fg[e] != ide) ok = false;
            if (cov0[e] != ide) ok = false;
            if (Qg[e] != ((i == j) ? q : 0.f)) ok = false;
        }
        if (tid < 256) {
            int i = tid >> 4, j = tid & 15;
            if (Rg[tid] != ((i == j) ? r : 0.f)) ok = false;
        }
        int special = __syncthreads_and((int)ok);
        if (!special) return;    // fallback kernels handle it
    }

    // ---- stash z tile to smem (frees registers through Jacobi) ----
    float4* zw = zb_dyn + w * (TT * OD / 4);
    zw[0 * 32 + lane] = zr0;  zw[1 * 32 + lane] = zr1;
    zw[2 * 32 + lane] = zr2;  zw[3 * 32 + lane] = zr3;
    zw[4 * 32 + lane] = zr4;  zw[5 * 32 + lane] = zr5;
    zw[6 * 32 + lane] = zr6;  zw[7 * 32 + lane] = zr7;

    // ---- load H to smem; init Wacc = I ----
    {
        int i = tid >> 5, j = tid & 31;
        Hs[i * 33 + j] = Hg[tid];
    }
    if (tid < 256) {
        int i = tid >> 4, m = tid & 15;
        Wacc[i * 17 + m] = (i == m) ? 1.f : 0.f;
    }
    __syncthreads();

    // ---- Gram matrix M = H H^T ----
    if (tid < 256) {
        int rr = tid >> 4, cc = tid & 15;
        float acc0 = 0.f, acc1 = 0.f;
        #pragma unroll
        for (int k = 0; k < SD; k += 2) {
            acc0 += Hs[rr * 33 + k] * Hs[cc * 33 + k];
            acc1 += Hs[rr * 33 + k + 1] * Hs[cc * 33 + k + 1];
        }
        Ms[rr * 17 + cc] = acc0 + acc1;
    }
    __syncthreads();

    // ---- global noise threshold: (1e-6 * mean eigenvalue)^2 ----
    if (tid == 0) {
        float tr = 0.f;
        #pragma unroll
        for (int i = 0; i < OD; i++) tr += Ms[i * 17 + i];
        float th = tr * (1e-6f / 16.f);
        thr2s = th * th;
        notconv = 0;
    }
    __syncthreads();

    // ---- two-sided Jacobi on M: warps 0..7, named barrier (256 threads) ----
    if (w < 8) {
        const float thr2 = thr2s;
        int cont = 1;
        for (int sweep = 0; sweep < 7 && cont; sweep++) {
            if (tid == 0) notconv = 0;
            BAR1();
            for (int rr = 0; rr < 15; rr++) {
                float c = 1.f, s = 0.f;
                bool rot;
                int p, qq;
                if (w == 0) { p = 0; qq = 1 + rr; }
                else { p = 1 + ((rr + w) % 15); qq = 1 + ((rr + 15 - w) % 15); }
                float mpp = Ms[p * 17 + p];
                float mqq = Ms[qq * 17 + qq];
                float mpq = Ms[p * 17 + qq];
                float g2 = mpq * mpq;
                rot = (g2 > thr2);
                if (rot) {
                    // fast-math rotation chain (MUFU rcp/rsq; ~1e-7 rel err)
                    float tau = __fdividef(mqq - mpp, 2.f * mpq);
                    float t2 = 1.f + tau * tau;
                    float st = t2 * rsqrtf(t2);             // ~sqrt(1+tau^2)
                    float tt = __fdividef((tau >= 0.f) ? 1.f : -1.f,
                                          fabsf(tau) + st);
                    c = rsqrtf(1.f + tt * tt);
                    s = c * tt;
                }
                if (lane == 0 && rot) notconv = 1;
                // row phase, split: lanes 0-15 -> Ms rows; lanes 16-31 -> Wacc rows
                if (rot) {
                    if (lane < 16) {
                        float mp = Ms[p * 17 + lane], mq = Ms[qq * 17 + lane];
                        Ms[p * 17 + lane]  = c * mp - s * mq;
                        Ms[qq * 17 + lane] = s * mp + c * mq;
                    } else {
                        int l = lane - 16;
                        float up = Wacc[p * 17 + l], uq = Wacc[qq * 17 + l];
                        Wacc[p * 17 + l]  = c * up - s * uq;
                        Wacc[qq * 17 + l] = s * up + c * uq;
                    }
                }
                BAR1();
                // col phase: M cols p,q  (M' = N G^T)
                if (rot && lane < 16) {
                    float vp = Ms[lane * 17 + p], vq = Ms[lane * 17 + qq];
                    Ms[lane * 17 + p]  = c * vp - s * vq;
                    Ms[lane * 17 + qq] = s * vp + c * vq;
                }
                BAR1();
            }
            cont = notconv;
            BAR1();   // all reads of notconv done before next sweep's zero
        }
        // sigma, U^T copy (within warps 0..7)
        if (tid < OD) sig[tid] = sqrtf(fmaxf(Ms[tid * 17 + tid], 0.f));
        if (tid < 256) Us[tid] = Wacc[(tid >> 4) * 17 + (tid & 15)];
    }
    __syncthreads();   // warps 8..15 waited here; sig/Us/Wacc/Hs now visible

    {
        // V[j][i] = (Wacc H)[i][j] / sig_i   (all 512 threads)
        int j = tid >> 4, i = tid & 15;
        float acc0 = 0.f, acc1 = 0.f;
        #pragma unroll
        for (int o = 0; o < OD; o += 2) {
            acc0 += Wacc[i * 17 + o] * Hs[o * 33 + j];
            acc1 += Wacc[i * 17 + o + 1] * Hs[(o + 1) * 33 + j];
        }
        float sg = sig[i];
        float rsg = (sg > 1e-20f) ? __fdividef(1.f, sg) : 0.f;
        Vs[j * 17 + i] = (acc0 + acc1) * rsg;
    }

    // ---- scalar gain recursion (threads 0..15), fast reciprocal ----
    if (tid < OD) {
        float sg = sig[tid];
        float lam = sg * sg;
        float p = 1.f;
        #pragma unroll 1
        for (int t = 0; t < TT; t++) {
            float pp = p + q;
            float dinv = __fdividef(1.f, lam * pp + r);
            float a = r * dinv;
            float kk = pp * sg * dinv;
            ab2[t * 16 + tid] = make_float2(a, kk);
            p = a * pp;
        }
    }
    __syncthreads();

    // ---- per-warp batch filter ----
    float Ureg[16], Vreg[16];
    #pragma unroll
    for (int m = 0; m < 16; m++) Ureg[m] = Us[i16 * 16 + m];
    #pragma unroll
    for (int m = 0; m < 16; m++) Vreg[m] = Vs[lane * 17 + m];

    // w[t] = U^T z[t], in place; ILP-4 partial accumulators
    #pragma unroll 4
    for (int it = 0; it < 32; it++) {
        const int t = it * 2 + (lane >> 4);
        float4 z0 = zw[t * 4 + 0];
        float4 z1 = zw[t * 4 + 1];
        float4 z2 = zw[t * 4 + 2];
        float4 z3 = zw[t * 4 + 3];
        float p0 = Ureg[0] * z0.x + Ureg[1] * z0.y + Ureg[2] * z0.z + Ureg[3] * z0.w;
        float p1 = Ureg[4] * z1.x + Ureg[5] * z1.y + Ureg[6] * z1.z + Ureg[7] * z1.w;
        float p2 = Ureg[8] * z2.x + Ureg[9] * z2.y + Ureg[10] * z2.z + Ureg[11] * z2.w;
        float p3 = Ureg[12] * z3.x + Ureg[13] * z3.y + Ureg[14] * z3.z + Ureg[15] * z3.w;
        float acc = (p0 + p1) + (p2 + p3);
        __syncwarp();
        ((float*)zw)[t * 16 + i16] = acc;
    }
    __syncwarp();

    // y0 = V^T x0 (component i16, duplicated across half-warps)
    float y = 0.f;
    #pragma unroll
    for (int j = 0; j < 32; j++)
        y += Vs[j * 17 + i16] * __shfl_sync(0xffffffffu, x0reg, j);

    // u[j] = x0[j] - sum_i V[j][i] y0_i
    float u = x0reg;
    #pragma unroll
    for (int m = 0; m < 16; m++)
        u -= Vreg[m] * __shfl_sync(0xffffffffu, y, m);

    // scalar scans: y_t = a y + k w (lanes 0..15), overwrite w with y
    if (lane < 16) {
        float* yw = (float*)zw;
        #pragma unroll 1
        for (int t = 0; t < TT; t++) {
            float2 akv = ab2[t * 16 + i16];
            float wv = yw[t * 16 + i16];
            y = akv.x * y + akv.y * wv;
            yw[t * 16 + i16] = y;
        }
    }
    __syncwarp();

    // out[t][j] = u[j] + sum_i V[j][i] y[t][i]; ILP-4 partials
    float* ob = out + (size_t)b * TT * SD;
    #pragma unroll 2
    for (int t = 0; t < TT; t++) {
        float4 y0 = zw[t * 4 + 0];
        float4 y1 = zw[t * 4 + 1];
        float4 y2 = zw[t * 4 + 2];
        float4 y3 = zw[t * 4 + 3];
        float p0 = Vreg[0] * y0.x + Vreg[1] * y0.y + Vreg[2] * y0.z + Vreg[3] * y0.w;
        float p1 = Vreg[4] * y1.x + Vreg[5] * y1.y + Vreg[6] * y1.z + Vreg[7] * y1.w;
        float p2 = Vreg[8] * y2.x + Vreg[9] * y2.y + Vreg[10] * y2.z + Vreg[11] * y2.w;
        float p3 = Vreg[12] * y3.x + Vreg[13] * y3.y + Vreg[14] * y3.z + Vreg[15] * y3.w;
        ob[t * SD + lane] = ((u + p0) + p1) + (p2 + p3);
    }
}

// ---------------------------------------------------------------------------
// FALLBACK phase 1 (verified) — performs specialness check, publishes g_special.
// ---------------------------------------------------------------------------
__global__ void __launch_bounds__(256, 1) phase1_kernel(
    const float* __restrict__ Fg, const float* __restrict__ Hg,
    const float* __restrict__ Qg, const float* __restrict__ Rg,
    const float* __restrict__ cov0)
{
    __shared__ float Fs[SD * P32];
    __shared__ float FT[SD * P32];
    __shared__ float Qs[SD * P32];
    __shared__ float Hs[OD * P32];
    __shared__ float Rs[OD * P16];
    __shared__ float Gs[OD * P32];
    __shared__ float Ps[SD * P32];
    __shared__ float Pp[SD * P32];
    __shared__ float T1[SD * P32];
    __shared__ float HPs[OD * P32];
    __shared__ float augA[OD * 49];
    __shared__ float augB[OD * 49];
    __shared__ float KPrev[OD * SD];
    __shared__ int fid;

    const int tid  = threadIdx.x;
    const int wid  = tid >> 5;
    const int lane = tid & 31;
    const int half = lane >> 4;
    const int rsel = wid + 8 * half;

    if (tid == 0) { fid = 1; g_tconv = TT - 1; }
    __syncthreads();

    const float q = Qg[0], r = Rg[0];
    {
        bool okF = true;
        bool okSp = (r > 0.f) && (q >= 0.f);
        #pragma unroll
        for (int s = 0; s < 4; s++) {
            int e = tid + s * 256;
            int i = e >> 5, j = e & 31;
            float ide = (i == j) ? 1.0f : 0.0f;
            float f = Fg[e];
            Fs[i * P32 + j] = f;
            FT[j * P32 + i] = f;
            Qs[i * P32 + j] = Qg[e];
            Ps[i * P32 + j] = cov0[e];
            if (f != ide) okF = false;
            if (Qg[e] != ((i == j) ? q : 0.f)) okSp = false;
            if (cov0[e] != ide) okSp = false;
        }
        if (!okF) fid = 0;
        #pragma unroll
        for (int s = 0; s < 2; s++) {
            int e = tid + s * 256;
            Hs[(e >> 5) * P32 + (e & 31)] = Hg[e];
        }
        Rs[(tid >> 4) * P16 + (tid & 15)] = Rg[tid];
        {
            int i = tid >> 4, j = tid & 15;
            if (Rg[tid] != ((i == j) ? r : 0.f)) okSp = false;
        }
        int special = __syncthreads_and((int)(okF && okSp));
        if (tid == 0) g_special = special;
        if (special) return;
    }
    __syncthreads();

    float hsel[SD];
    #pragma unroll
    for (int k = 0; k < SD; k++) hsel[k] = Hs[rsel * P32 + k];

    #pragma unroll
    for (int s = 0; s < 2; s++) {
        int e = tid + s * 256;
        int o = e >> 5, j = e & 31;
        float acc = 0.f;
        #pragma unroll
        for (int k = 0; k < SD; k++) acc += Hs[o * P32 + k] * FT[j * P32 + k];
        Gs[o * P32 + j] = acc;
    }
    const int ident = fid;
    __syncthreads();

    float Greg[OD * 4];
    #pragma unroll
    for (int o = 0; o < OD; o++) {
        Greg[o * 4 + 0] = Gs[o * P32 + wid];
        Greg[o * 4 + 1] = Gs[o * P32 + wid + 8];
        Greg[o * 4 + 2] = Gs[o * P32 + wid + 16];
        Greg[o * 4 + 3] = Gs[o * P32 + wid + 24];
    }

    #pragma unroll 1
    for (int t = 0; t < TT; t++) {
        if (ident) {
            #pragma unroll
            for (int s = 0; s < 4; s++) {
                int e = tid + s * 256;
                int idx = (e >> 5) * P32 + (e & 31);
                Pp[idx] = Ps[idx] + Qs[idx];
            }
        } else {
            #pragma unroll
            for (int s = 0; s < 4; s++) {
                int e = tid + s * 256;
                int i = e >> 5, j = e & 31;
                float acc = 0.f;
                #pragma unroll
                for (int k = 0; k < SD; k++) acc += Fs[i * P32 + k] * Ps[k * P32 + j];
                T1[i * P32 + j] = acc;
            }
            __syncthreads();
            #pragma unroll
            for (int s = 0; s < 4; s++) {
                int e = tid + s * 256;
                int i = e >> 5, j = e & 31;
                float acc = Qs[i * P32 + j];
                #pragma unroll
                for (int k = 0; k < SD; k++) acc += T1[i * P32 + k] * Fs[j * P32 + k];
                Pp[i * P32 + j] = acc;
            }
        }
        __syncthreads();

        {
            const int j0 = lane & 15;
            float a0 = 0.f, a1 = 0.f;
            #pragma unroll
            for (int k = 0; k < SD; k++) {
                float p0 = Pp[k * P32 + j0];
                float p1 = Pp[k * P32 + j0 + 16];
                a0 += hsel[k] * p0;
                a1 += hsel[k] * p1;
            }
            HPs[rsel * P32 + j0]      = a0;
            HPs[rsel * P32 + j0 + 16] = a1;
        }
        __syncthreads();

        {
            const int rr = lane & 15;
            float acc = Rs[rr * P16 + rsel];
            #pragma unroll
            for (int k = 0; k < SD; k++) acc += HPs[rr * P32 + k] * hsel[k];
            augA[rr * 49 + rsel] = acc;
        }
        #pragma unroll
        for (int s = 0; s < 2; s++) {
            int e = tid + s * 256;
            int rr = e >> 5, i = e & 31;
            augA[rr * 49 + 16 + i] = HPs[rr * P32 + i];
        }
        __syncthreads();

        #pragma unroll 1
        for (int rd = 0; rd < 8; rd++) {
            const float* cu = (rd & 1) ? augB : augA;
            float* nx = (rd & 1) ? augA : augB;
            const int p = 2 * rd;
            const float a  = cu[p * 49 + p];
            const float bb = cu[p * 49 + p + 1];
            const float cc = cu[(p + 1) * 49 + p];
            const float dd = cu[(p + 1) * 49 + p + 1];
            const float rdet = 1.0f / (a * dd - bb * cc);
            const int aw = 46 - 2 * rd;
            const int cb = p + 2;
            const int tot = OD * aw;
            for (int e = tid; e < tot; e += 256) {
                int rr = e / aw;
                int c = cb + (e - rr * aw);
                float rp = cu[p * 49 + c];
                float rq = cu[(p + 1) * 49 + c];
                float np = (dd * rp - bb * rq) * rdet;
                float nq = (a * rq - cc * rp) * rdet;
                float val;
                if (rr == p)          val = np;
                else if (rr == p + 1) val = nq;
                else                  val = cu[rr * 49 + c] - cu[rr * 49 + p] * np - cu[rr * 49 + p + 1] * nq;
                nx[rr * 49 + c] = val;
            }
            __syncthreads();
        }

        bool okl = true;
        #pragma unroll
        for (int s = 0; s < 2; s++) {
            int e = tid + s * 256;
            int o = e >> 5, i = e & 31;
            float kv = augA[o * 49 + 16 + i];
            g_W[t][(SD + o) * SD + i] = kv;
            float pv = KPrev[e];
            KPrev[e] = kv;
            if (fabsf(kv - pv) >= 3e-6f) okl = false;
        }

        {
            const int i = lane, jg = wid;
            float w0 = FT[jg * P32 + i];
            float w1 = FT[(jg + 8) * P32 + i];
            float w2 = FT[(jg + 16) * P32 + i];
            float w3 = FT[(jg + 24) * P32 + i];
            #pragma unroll
            for (int o = 0; o < OD; o++) {
                float kv = augA[o * 49 + 16 + i];
                w0 -= Greg[o * 4 + 0] * kv;
                w1 -= Greg[o * 4 + 1] * kv;
                w2 -= Greg[o * 4 + 2] * kv;
                w3 -= Greg[o * 4 + 3] * kv;
            }
            float* wt = g_W[t];
            wt[jg * SD + i]        = w0;
            wt[(jg + 8) * SD + i]  = w1;
            wt[(jg + 16) * SD + i] = w2;
            wt[(jg + 24) * SD + i] = w3;
        }

        {
            const int j = lane, ig = wid;
            float p0 = Pp[ig * P32 + j];
            float p1 = Pp[(ig + 8) * P32 + j];
            float p2 = Pp[(ig + 16) * P32 + j];
            float p3 = Pp[(ig + 24) * P32 + j];
            #pragma unroll
            for (int o = 0; o < OD; o++) {
                float hv = HPs[o * P32 + j];
                p0 -= augA[o * 49 + 16 + ig] * hv;
                p1 -= augA[o * 49 + 16 + ig + 8] * hv;
                p2 -= augA[o * 49 + 16 + ig + 16] * hv;
                p3 -= augA[o * 49 + 16 + ig + 24] * hv;
            }
            Ps[ig * P32 + j]        = p0;
            Ps[(ig + 8) * P32 + j]  = p1;
            Ps[(ig + 16) * P32 + j] = p2;
            Ps[(ig + 24) * P32 + j] = p3;
        }

        int conv = __syncthreads_and((int)(okl && (t > 0)));
        if (conv) {
            if (tid == 0) g_tconv = t;
            break;
        }
    }
}

// ---------------------------------------------------------------------------
// FALLBACK phase 2 (verified) — no-op if g_special.
// ---------------------------------------------------------------------------
__global__ void __launch_bounds__(256, 1) phase2_kernel(
    const float* __restrict__ x0g,
    const float* __restrict__ meas,
    float* __restrict__ out)
{
    if (g_special) return;

    __shared__ float Wb[2][48 * SD];
    __shared__ float xs[8][2][SD + 1];
    __shared__ float zs[8][2][OD];

    const int tid  = threadIdx.x;
    const int bl   = tid >> 5;
    const int lane = tid & 31;
    const int b0   = (blockIdx.x * 8 + bl) * 2;
    const int b1   = b0 + 1;
    const int lzb  = (lane < OD) ? b0 : b1;
    const int lz   = lane & 15;
    const int tconv = g_tconv;

    xs[bl][0][lane] = x0g[b0 * SD + lane];
    xs[bl][1][lane] = x0g[b1 * SD + lane];
    zs[bl][lane >> 4][lz] = meas[(lzb * TT + 0) * OD + lz];
    {
        const float4* gw = (const float4*)g_W[0];
        float4* d = (float4*)Wb[0];
        d[tid] = gw[tid];
        if (tid < 128) d[256 + tid] = gw[256 + tid];
    }
    __syncthreads();

    int cur = 0;
    int tW = 0;

    #pragma unroll 1
    for (int t = 0; t < TT; t++) {
        int tn = (t + 1 < TT) ? ((t + 1 < tconv) ? (t + 1) : tconv) : tW;
        const bool stage = (tn != tW);

        float4 n0, n1;
        float zn;
        if (stage) {
            const float4* gw = (const float4*)g_W[tn];
            n0 = gw[tid];
            if (tid < 128) n1 = gw[256 + tid];
        }
        if (t + 1 < TT) zn = meas[(lzb * TT + (t + 1)) * OD + lz];

        const float* AT = Wb[cur];
        const float* KT = Wb[cur] + SD * SD;
        float a0 = 0.f, a1 = 0.f, c0 = 0.f, c1 = 0.f;
        #pragma unroll
        for (int j = 0; j < SD; j += 2) {
            float w0 = AT[j * SD + lane];
            float w1 = AT[(j + 1) * SD + lane];
            a0 += w0 * xs[bl][0][j];
            c0 += w0 * xs[bl][1][j];
            a1 += w1 * xs[bl][0][j + 1];
            c1 += w1 * xs[bl][1][j + 1];
        }
        #pragma unroll
        for (int o = 0; o < OD; o += 2) {
            float w0 = KT[o * SD + lane];
            float w1 = KT[(o + 1) * SD + lane];
            a0 += w0 * zs[bl][0][o];
            c0 += w0 * zs[bl][1][o];
            a1 += w1 * zs[bl][0][o + 1];
            c1 += w1 * zs[bl][1][o + 1];
        }
        const float xa = a0 + a1;
        const float xc = c0 + c1;
        out[(b0 * TT + t) * SD + lane] = xa;
        out[(b1 * TT + t) * SD + lane] = xc;
        __syncthreads();

        xs[bl][0][lane] = xa;
        xs[bl][1][lane] = xc;
        if (t + 1 < TT) zs[bl][lane >> 4][lz] = zn;
        if (stage) {
            float4* d = (float4*)Wb[cur ^ 1];
            d[tid] = n0;
            if (tid < 128) d[256 + tid] = n1;
            cur ^= 1;
            tW = tn;
        }
        __syncthreads();
    }
}

// ---------------------------------------------------------------------------
extern "C" void kernel_launch(void* const* d_in, const int* in_sizes, int n_in,
                              void* d_out, int out_size) {
    const float* state0 = (const float*)d_in[0];  // (B, 32)
    const float* cov0   = (const float*)d_in[1];  // (B, 32, 32)
    const float* meas   = (const float*)d_in[2];  // (B, 64, 16)
    const float* F      = (const float*)d_in[3];  // (32, 32)
    const float* H      = (const float*)d_in[4];  // (16, 32)
    const float* Q      = (const float*)d_in[5];  // (32, 32)
    const float* R      = (const float*)d_in[6];  // (16, 16)
    float* out = (float*)d_out;                   // (B, 64, 32)
    (void)in_sizes; (void)n_in; (void)out_size;

    const int dyn = 16 * TT * OD * (int)sizeof(float);   // 64 KB zb
    cudaFuncSetAttribute(fused_kernel,
                         cudaFuncAttributeMaxDynamicSharedMemorySize, dyn);

    fused_kernel<<<NB / 16, 512, dyn>>>(state0, meas, out, F, H, Q, R, cov0);
    phase1_kernel<<<1, 256>>>(F, H, Q, R, cov0);        // no-op if special
    phase2_kernel<<<NB / 16, 256>>>(state0, meas, out); // no-op if special
}

// round 14
// speedup vs baseline: 1.1722x; 1.1722x over previous
#include <cuda_runtime.h>
#include <math.h>

// Kalman filter B=2048, T=64, STATE=32, OBS=16.
// SPECIAL PATH (F=I, Q=qI, R=rI, cov0=I — verified per CTA):
//   fused_kernel: per-CTA Gram-matrix Jacobi eigendecomp of HH^T + scalar gain
//   recursions, then 16 warps each filter one batch. Scans use a separate
//   w/y smem buffer (no in-place hazards -> no per-iter syncwarp).
// FALLBACK: verified phase1/phase2 (phase1 publishes g_special).

#define SD 32
#define OD 16
#define TT 64
#define NB 2048
#define P32 33
#define P16 17

#define BAR1() asm volatile("bar.sync 1, 256;" ::: "memory")

__device__ int g_special;
__device__ __align__(16) float g_W[TT][48 * SD];
__device__ int g_tconv;

// ---------------------------------------------------------------------------
// Fused special-path kernel
// ---------------------------------------------------------------------------
__global__ void __launch_bounds__(512, 1) fused_kernel(
    const float* __restrict__ x0g,
    const float* __restrict__ meas,   // (B, T, 16)
    float* __restrict__ out,          // (B, T, 32)
    const float* __restrict__ Fg, const float* __restrict__ Hg,
    const float* __restrict__ Qg, const float* __restrict__ Rg,
    const float* __restrict__ cov0)
{
    // dyn smem: [0, 64KB): z tiles (16 warps x 256 float4)
    //           [64KB, 128KB): w/y buffer (16 warps x 1024 float)
    extern __shared__ float4 zb_dyn[];

    __shared__ float Hs[OD * 33];           // H rows (kept for V recovery)
    __shared__ float Ms[OD * 17];           // Gram matrix H H^T
    __shared__ float Wacc[OD * 17];         // accumulated rotations = U^T
    __shared__ float sig[OD];
    __shared__ float2 ab2[TT * OD];         // (a_i,t , k_i,t)
    __shared__ float Us[OD * OD];
    __shared__ float Vs[SD * 17];
    __shared__ float thr2s;
    __shared__ int notconv;

    const int tid  = threadIdx.x;
    const int w    = tid >> 5;
    const int lane = tid & 31;
    const int i16  = lane & 15;
    const float q = Qg[0], r = Rg[0];

    // ---- issue batch loads EARLY ----
    const int b = blockIdx.x * 16 + w;
    const float4* zg = (const float4*)(meas + (size_t)b * TT * OD);
    float4 zr0 = zg[0 * 32 + lane];
    float4 zr1 = zg[1 * 32 + lane];
    float4 zr2 = zg[2 * 32 + lane];
    float4 zr3 = zg[3 * 32 + lane];
    float4 zr4 = zg[4 * 32 + lane];
    float4 zr5 = zg[5 * 32 + lane];
    float4 zr6 = zg[6 * 32 + lane];
    float4 zr7 = zg[7 * 32 + lane];
    float x0reg = x0g[b * SD + lane];

    // ---- specialness check (all 512 threads) ----
    {
        bool ok = (r > 0.f) && (q >= 0.f);
        #pragma unroll
        for (int s = 0; s < 2; s++) {
            int e = tid + s * 512;
            int i = e >> 5, j = e & 31;
            float ide = (i == j) ? 1.f : 0.f;
            if (Fg[e] != ide) ok = false;
            if (cov0[e] != ide) ok = false;
            if (Qg[e] != ((i == j) ? q : 0.f)) ok = false;
        }
        if (tid < 256) {
            int i = tid >> 4, j = tid & 15;
            if (Rg[tid] != ((i == j) ? r : 0.f)) ok = false;
        }
        int special = __syncthreads_and((int)ok);
        if (!special) return;    // fallback kernels handle it
    }

    // ---- stash z tile to smem ----
    float4* zw = zb_dyn + w * (TT * OD / 4);
    zw[0 * 32 + lane] = zr0;  zw[1 * 32 + lane] = zr1;
    zw[2 * 32 + lane] = zr2;  zw[3 * 32 + lane] = zr3;
    zw[4 * 32 + lane] = zr4;  zw[5 * 32 + lane] = zr5;
    zw[6 * 32 + lane] = zr6;  zw[7 * 32 + lane] = zr7;
    float* wwt = ((float*)(zb_dyn + 16 * (TT * OD / 4))) + w * (TT * OD);

    // ---- load H to smem; init Wacc = I ----
    {
        int i = tid >> 5, j = tid & 31;
        Hs[i * 33 + j] = Hg[tid];
    }
    if (tid < 256) {
        int i = tid >> 4, m = tid & 15;
        Wacc[i * 17 + m] = (i == m) ? 1.f : 0.f;
    }
    __syncthreads();

    // ---- Gram matrix M = H H^T ----
    if (tid < 256) {
        int rr = tid >> 4, cc = tid & 15;
        float acc0 = 0.f, acc1 = 0.f;
        #pragma unroll
        for (int k = 0; k < SD; k += 2) {
            acc0 += Hs[rr * 33 + k] * Hs[cc * 33 + k];
            acc1 += Hs[rr * 33 + k + 1] * Hs[cc * 33 + k + 1];
        }
        Ms[rr * 17 + cc] = acc0 + acc1;
    }
    __syncthreads();

    // ---- global noise threshold: (1e-6 * mean eigenvalue)^2 ----
    if (tid == 0) {
        float tr = 0.f;
        #pragma unroll
        for (int i = 0; i < OD; i++) tr += Ms[i * 17 + i];
        float th = tr * (1e-6f / 16.f);
        thr2s = th * th;
        notconv = 0;
    }
    __syncthreads();

    // ---- two-sided Jacobi on M: warps 0..7, named barrier (256 threads) ----
    if (w < 8) {
        const float thr2 = thr2s;
        int cont = 1;
        for (int sweep = 0; sweep < 7 && cont; sweep++) {
            if (tid == 0) notconv = 0;
            int wrot = 0;                       // per-warp register flag
            BAR1();
            for (int rr = 0; rr < 15; rr++) {
                float c = 1.f, s = 0.f;
                bool rot;
                int p, qq;
                if (w == 0) { p = 0; qq = 1 + rr; }
                else { p = 1 + ((rr + w) % 15); qq = 1 + ((rr + 15 - w) % 15); }
                float mpp = Ms[p * 17 + p];
                float mqq = Ms[qq * 17 + qq];
                float mpq = Ms[p * 17 + qq];
                float g2 = mpq * mpq;
                rot = (g2 > thr2);
                wrot |= (int)rot;
                if (rot) {
                    float tau = __fdividef(mqq - mpp, 2.f * mpq);
                    float t2 = 1.f + tau * tau;
                    float st = t2 * rsqrtf(t2);             // ~sqrt(1+tau^2)
                    float tt = __fdividef((tau >= 0.f) ? 1.f : -1.f,
                                          fabsf(tau) + st);
                    c = rsqrtf(1.f + tt * tt);
                    s = c * tt;
                }
                // row phase, split: lanes 0-15 -> Ms rows; lanes 16-31 -> Wacc rows
                if (rot) {
                    if (lane < 16) {
                        float mp = Ms[p * 17 + lane], mq = Ms[qq * 17 + lane];
                        Ms[p * 17 + lane]  = c * mp - s * mq;
                        Ms[qq * 17 + lane] = s * mp + c * mq;
                    } else {
                        int l = lane - 16;
                        float up = Wacc[p * 17 + l], uq = Wacc[qq * 17 + l];
                        Wacc[p * 17 + l]  = c * up - s * uq;
                        Wacc[qq * 17 + l] = s * up + c * uq;
                    }
                }
                BAR1();
                // col phase: M cols p,q  (M' = N G^T)
                if (rot && lane < 16) {
                    float vp = Ms[lane * 17 + p], vq = Ms[lane * 17 + qq];
                    Ms[lane * 17 + p]  = c * vp - s * vq;
                    Ms[lane * 17 + qq] = s * vp + c * vq;
                }
                BAR1();
            }
            if (lane == 0 && wrot) notconv = 1;
            BAR1();
            cont = notconv;
            BAR1();   // all reads of notconv done before next sweep's zero
        }
        // sigma, U^T copy (within warps 0..7)
        if (tid < OD) sig[tid] = sqrtf(fmaxf(Ms[tid * 17 + tid], 0.f));
        if (tid < 256) Us[tid] = Wacc[(tid >> 4) * 17 + (tid & 15)];
    }
    __syncthreads();   // warps 8..15 waited here; sig/Us/Wacc/Hs now visible

    {
        // V[j][i] = (Wacc H)[i][j] / sig_i   (all 512 threads)
        int j = tid >> 4, i = tid & 15;
        float acc0 = 0.f, acc1 = 0.f;
        #pragma unroll
        for (int o = 0; o < OD; o += 2) {
            acc0 += Wacc[i * 17 + o] * Hs[o * 33 + j];
            acc1 += Wacc[i * 17 + o + 1] * Hs[(o + 1) * 33 + j];
        }
        float sg = sig[i];
        float rsg = (sg > 1e-20f) ? __fdividef(1.f, sg) : 0.f;
        Vs[j * 17 + i] = (acc0 + acc1) * rsg;
    }

    // ---- scalar gain recursion (threads 0..15), fast reciprocal ----
    if (tid < OD) {
        float sg = sig[tid];
        float lam = sg * sg;
        float p = 1.f;
        #pragma unroll 1
        for (int t = 0; t < TT; t++) {
            float pp = p + q;
            float dinv = __fdividef(1.f, lam * pp + r);
            float a = r * dinv;
            float kk = pp * sg * dinv;
            ab2[t * 16 + tid] = make_float2(a, kk);
            p = a * pp;
        }
    }
    __syncthreads();

    // ---- per-warp batch filter ----
    float Ureg[16], Vreg[16];
    #pragma unroll
    for (int m = 0; m < 16; m++) Ureg[m] = Us[i16 * 16 + m];
    #pragma unroll
    for (int m = 0; m < 16; m++) Vreg[m] = Vs[lane * 17 + m];

    // w[t] = U^T z[t] -> separate buffer; no per-iter syncwarp, fully pipelined
    #pragma unroll 8
    for (int it = 0; it < 32; it++) {
        const int t = it * 2 + (lane >> 4);
        float4 z0 = zw[t * 4 + 0];
        float4 z1 = zw[t * 4 + 1];
        float4 z2 = zw[t * 4 + 2];
        float4 z3 = zw[t * 4 + 3];
        float p0 = Ureg[0] * z0.x + Ureg[1] * z0.y + Ureg[2] * z0.z + Ureg[3] * z0.w;
        float p1 = Ureg[4] * z1.x + Ureg[5] * z1.y + Ureg[6] * z1.z + Ureg[7] * z1.w;
        float p2 = Ureg[8] * z2.x + Ureg[9] * z2.y + Ureg[10] * z2.z + Ureg[11] * z2.w;
        float p3 = Ureg[12] * z3.x + Ureg[13] * z3.y + Ureg[14] * z3.z + Ureg[15] * z3.w;
        wwt[t * 16 + i16] = (p0 + p1) + (p2 + p3);
    }
    __syncwarp();

    // y0 = V^T x0 (component i16, duplicated across half-warps)
    float y = 0.f;
    #pragma unroll
    for (int j = 0; j < 32; j++)
        y += Vs[j * 17 + i16] * __shfl_sync(0xffffffffu, x0reg, j);

    // u[j] = x0[j] - sum_i V[j][i] y0_i
    float u = x0reg;
    #pragma unroll
    for (int m = 0; m < 16; m++)
        u -= Vreg[m] * __shfl_sync(0xffffffffu, y, m);

    // scalar scans: y_t = a y + k w (lanes 0..15), overwrite w with y
    if (lane < 16) {
        #pragma unroll 1
        for (int t = 0; t < TT; t++) {
            float2 akv = ab2[t * 16 + i16];
            float wv = wwt[t * 16 + i16];
            y = akv.x * y + akv.y * wv;
            wwt[t * 16 + i16] = y;
        }
    }
    __syncwarp();

    // out[t][j] = u[j] + sum_i V[j][i] y[t][i]; 2 timesteps per iteration
    float* ob = out + (size_t)b * TT * SD;
    const float4* wv4 = (const float4*)wwt;
    #pragma unroll 4
    for (int t = 0; t < TT; t += 2) {
        float4 a0 = wv4[t * 4 + 0];
        float4 a1 = wv4[t * 4 + 1];
        float4 a2 = wv4[t * 4 + 2];
        float4 a3 = wv4[t * 4 + 3];
        float4 b0 = wv4[(t + 1) * 4 + 0];
        float4 b1 = wv4[(t + 1) * 4 + 1];
        float4 b2 = wv4[(t + 1) * 4 + 2];
        float4 b3 = wv4[(t + 1) * 4 + 3];
        float pa = Vreg[0] * a0.x + Vreg[1] * a0.y + Vreg[2] * a0.z + Vreg[3] * a0.w
                 + Vreg[4] * a1.x + Vreg[5] * a1.y + Vreg[6] * a1.z + Vreg[7] * a1.w
                 + Vreg[8] * a2.x + Vreg[9] * a2.y + Vreg[10] * a2.z + Vreg[11] * a2.w
                 + Vreg[12] * a3.x + Vreg[13] * a3.y + Vreg[14] * a3.z + Vreg[15] * a3.w;
        float pb = Vreg[0] * b0.x + Vreg[1] * b0.y + Vreg[2] * b0.z + Vreg[3] * b0.w
                 + Vreg[4] * b1.x + Vreg[5] * b1.y + Vreg[6] * b1.z + Vreg[7] * b1.w
                 + Vreg[8] * b2.x + Vreg[9] * b2.y + Vreg[10] * b2.z + Vreg[11] * b2.w
                 + Vreg[12] * b3.x + Vreg[13] * b3.y + Vreg[14] * b3.z + Vreg[15] * b3.w;
        ob[t * SD + lane]       = u + pa;
        ob[(t + 1) * SD + lane] = u + pb;
    }
}

// ---------------------------------------------------------------------------
// FALLBACK phase 1 (verified) — performs specialness check, publishes g_special.
// ---------------------------------------------------------------------------
__global__ void __launch_bounds__(256, 1) phase1_kernel(
    const float* __restrict__ Fg, const float* __restrict__ Hg,
    const float* __restrict__ Qg, const float* __restrict__ Rg,
    const float* __restrict__ cov0)
{
    __shared__ float Fs[SD * P32];
    __shared__ float FT[SD * P32];
    __shared__ float Qs[SD * P32];
    __shared__ float Hs[OD * P32];
    __shared__ float Rs[OD * P16];
    __shared__ float Gs[OD * P32];
    __shared__ float Ps[SD * P32];
    __shared__ float Pp[SD * P32];
    __shared__ float T1[SD * P32];
    __shared__ float HPs[OD * P32];
    __shared__ float augA[OD * 49];
    __shared__ float augB[OD * 49];
    __shared__ float KPrev[OD * SD];
    __shared__ int fid;

    const int tid  = threadIdx.x;
    const int wid  = tid >> 5;
    const int lane = tid & 31;
    const int half = lane >> 4;
    const int rsel = wid + 8 * half;

    if (tid == 0) { fid = 1; g_tconv = TT - 1; }
    __syncthreads();

    const float q = Qg[0], r = Rg[0];
    {
        bool okF = true;
        bool okSp = (r > 0.f) && (q >= 0.f);
        #pragma unroll
        for (int s = 0; s < 4; s++) {
            int e = tid + s * 256;
            int i = e >> 5, j = e & 31;
            float ide = (i == j) ? 1.0f : 0.0f;
            float f = Fg[e];
            Fs[i * P32 + j] = f;
            FT[j * P32 + i] = f;
            Qs[i * P32 + j] = Qg[e];
            Ps[i * P32 + j] = cov0[e];
            if (f != ide) okF = false;
            if (Qg[e] != ((i == j) ? q : 0.f)) okSp = false;
            if (cov0[e] != ide) okSp = false;
        }
        if (!okF) fid = 0;
        #pragma unroll
        for (int s = 0; s < 2; s++) {
            int e = tid + s * 256;
            Hs[(e >> 5) * P32 + (e & 31)] = Hg[e];
        }
        Rs[(tid >> 4) * P16 + (tid & 15)] = Rg[tid];
        {
            int i = tid >> 4, j = tid & 15;
            if (Rg[tid] != ((i == j) ? r : 0.f)) okSp = false;
        }
        int special = __syncthreads_and((int)(okF && okSp));
        if (tid == 0) g_special = special;
        if (special) return;
    }
    __syncthreads();

    float hsel[SD];
    #pragma unroll
    for (int k = 0; k < SD; k++) hsel[k] = Hs[rsel * P32 + k];

    #pragma unroll
    for (int s = 0; s < 2; s++) {
        int e = tid + s * 256;
        int o = e >> 5, j = e & 31;
        float acc = 0.f;
        #pragma unroll
        for (int k = 0; k < SD; k++) acc += Hs[o * P32 + k] * FT[j * P32 + k];
        Gs[o * P32 + j] = acc;
    }
    const int ident = fid;
    __syncthreads();

    float Greg[OD * 4];
    #pragma unroll
    for (int o = 0; o < OD; o++) {
        Greg[o * 4 + 0] = Gs[o * P32 + wid];
        Greg[o * 4 + 1] = Gs[o * P32 + wid + 8];
        Greg[o * 4 + 2] = Gs[o * P32 + wid + 16];
        Greg[o * 4 + 3] = Gs[o * P32 + wid + 24];
    }

    #pragma unroll 1
    for (int t = 0; t < TT; t++) {
        if (ident) {
            #pragma unroll
            for (int s = 0; s < 4; s++) {
                int e = tid + s * 256;
                int idx = (e >> 5) * P32 + (e & 31);
                Pp[idx] = Ps[idx] + Qs[idx];
            }
        } else {
            #pragma unroll
            for (int s = 0; s < 4; s++) {
                int e = tid + s * 256;
                int i = e >> 5, j = e & 31;
                float acc = 0.f;
                #pragma unroll
                for (int k = 0; k < SD; k++) acc += Fs[i * P32 + k] * Ps[k * P32 + j];
                T1[i * P32 + j] = acc;
            }
            __syncthreads();
            #pragma unroll
            for (int s = 0; s < 4; s++) {
                int e = tid + s * 256;
                int i = e >> 5, j = e & 31;
                float acc = Qs[i * P32 + j];
                #pragma unroll
                for (int k = 0; k < SD; k++) acc += T1[i * P32 + k] * Fs[j * P32 + k];
                Pp[i * P32 + j] = acc;
            }
        }
        __syncthreads();

        {
            const int j0 = lane & 15;
            float a0 = 0.f, a1 = 0.f;
            #pragma unroll
            for (int k = 0; k < SD; k++) {
                float p0 = Pp[k * P32 + j0];
                float p1 = Pp[k * P32 + j0 + 16];
                a0 += hsel[k] * p0;
                a1 += hsel[k] * p1;
            }
            HPs[rsel * P32 + j0]      = a0;
            HPs[rsel * P32 + j0 + 16] = a1;
        }
        __syncthreads();

        {
            const int rr = lane & 15;
            float acc = Rs[rr * P16 + rsel];
            #pragma unroll
            for (int k = 0; k < SD; k++) acc += HPs[rr * P32 + k] * hsel[k];
            augA[rr * 49 + rsel] = acc;
        }
        #pragma unroll
        for (int s = 0; s < 2; s++) {
            int e = tid + s * 256;
            int rr = e >> 5, i = e & 31;
            augA[rr * 49 + 16 + i] = HPs[rr * P32 + i];
        }
        __syncthreads();

        #pragma unroll 1
        for (int rd = 0; rd < 8; rd++) {
            const float* cu = (rd & 1) ? augB : augA;
            float* nx = (rd & 1) ? augA : augB;
            const int p = 2 * rd;
            const float a  = cu[p * 49 + p];
            const float bb = cu[p * 49 + p + 1];
            const float cc = cu[(p + 1) * 49 + p];
            const float dd = cu[(p + 1) * 49 + p + 1];
            const float rdet = 1.0f / (a * dd - bb * cc);
            const int aw = 46 - 2 * rd;
            const int cb = p + 2;
            const int tot = OD * aw;
            for (int e = tid; e < tot; e += 256) {
                int rr = e / aw;
                int c = cb + (e - rr * aw);
                float rp = cu[p * 49 + c];
                float rq = cu[(p + 1) * 49 + c];
                float np = (dd * rp - bb * rq) * rdet;
                float nq = (a * rq - cc * rp) * rdet;
                float val;
                if (rr == p)          val = np;
                else if (rr == p + 1) val = nq;
                else                  val = cu[rr * 49 + c] - cu[rr * 49 + p] * np - cu[rr * 49 + p + 1] * nq;
                nx[rr * 49 + c] = val;
            }
            __syncthreads();
        }

        bool okl = true;
        #pragma unroll
        for (int s = 0; s < 2; s++) {
            int e = tid + s * 256;
            int o = e >> 5, i = e & 31;
            float kv = augA[o * 49 + 16 + i];
            g_W[t][(SD + o) * SD + i] = kv;
            float pv = KPrev[e];
            KPrev[e] = kv;
            if (fabsf(kv - pv) >= 3e-6f) okl = false;
        }

        {
            const int i = lane, jg = wid;
            float w0 = FT[jg * P32 + i];
            float w1 = FT[(jg + 8) * P32 + i];
            float w2 = FT[(jg + 16) * P32 + i];
            float w3 = FT[(jg + 24) * P32 + i];
            #pragma unroll
            for (int o = 0; o < OD; o++) {
                float kv = augA[o * 49 + 16 + i];
                w0 -= Greg[o * 4 + 0] * kv;
                w1 -= Greg[o * 4 + 1] * kv;
                w2 -= Greg[o * 4 + 2] * kv;
                w3 -= Greg[o * 4 + 3] * kv;
            }
            float* wt = g_W[t];
            wt[jg * SD + i]        = w0;
            wt[(jg + 8) * SD + i]  = w1;
            wt[(jg + 16) * SD + i] = w2;
            wt[(jg + 24) * SD + i] = w3;
        }

        {
            const int j = lane, ig = wid;
            float p0 = Pp[ig * P32 + j];
            float p1 = Pp[(ig + 8) * P32 + j];
            float p2 = Pp[(ig + 16) * P32 + j];
            float p3 = Pp[(ig + 24) * P32 + j];
            #pragma unroll
            for (int o = 0; o < OD; o++) {
                float hv = HPs[o * P32 + j];
                p0 -= augA[o * 49 + 16 + ig] * hv;
                p1 -= augA[o * 49 + 16 + ig + 8] * hv;
                p2 -= augA[o * 49 + 16 + ig + 16] * hv;
                p3 -= augA[o * 49 + 16 + ig + 24] * hv;
            }
            Ps[ig * P32 + j]        = p0;
            Ps[(ig + 8) * P32 + j]  = p1;
            Ps[(ig + 16) * P32 + j] = p2;
            Ps[(ig + 24) * P32 + j] = p3;
        }

        int conv = __syncthreads_and((int)(okl && (t > 0)));
        if (conv) {
            if (tid == 0) g_tconv = t;
            break;
        }
    }
}

// ---------------------------------------------------------------------------
// FALLBACK phase 2 (verified) — no-op if g_special.
// ---------------------------------------------------------------------------
__global__ void __launch_bounds__(256, 1) phase2_kernel(
    const float* __restrict__ x0g,
    const float* __restrict__ meas,
    float* __restrict__ out)
{
    if (g_special) return;

    __shared__ float Wb[2][48 * SD];
    __shared__ float xs[8][2][SD + 1];
    __shared__ float zs[8][2][OD];

    const int tid  = threadIdx.x;
    const int bl   = tid >> 5;
    const int lane = tid & 31;
    const int b0   = (blockIdx.x * 8 + bl) * 2;
    const int b1   = b0 + 1;
    const int lzb  = (lane < OD) ? b0 : b1;
    const int lz   = lane & 15;
    const int tconv = g_tconv;

    xs[bl][0][lane] = x0g[b0 * SD + lane];
    xs[bl][1][lane] = x0g[b1 * SD + lane];
    zs[bl][lane >> 4][lz] = meas[(lzb * TT + 0) * OD + lz];
    {
        const float4* gw = (const float4*)g_W[0];
        float4* d = (float4*)Wb[0];
        d[tid] = gw[tid];
        if (tid < 128) d[256 + tid] = gw[256 + tid];
    }
    __syncthreads();

    int cur = 0;
    int tW = 0;

    #pragma unroll 1
    for (int t = 0; t < TT; t++) {
        int tn = (t + 1 < TT) ? ((t + 1 < tconv) ? (t + 1) : tconv) : tW;
        const bool stage = (tn != tW);

        float4 n0, n1;
        float zn;
        if (stage) {
            const float4* gw = (const float4*)g_W[tn];
            n0 = gw[tid];
            if (tid < 128) n1 = gw[256 + tid];
        }
        if (t + 1 < TT) zn = meas[(lzb * TT + (t + 1)) * OD + lz];

        const float* AT = Wb[cur];
        const float* KT = Wb[cur] + SD * SD;
        float a0 = 0.f, a1 = 0.f, c0 = 0.f, c1 = 0.f;
        #pragma unroll
        for (int j = 0; j < SD; j += 2) {
            float w0 = AT[j * SD + lane];
            float w1 = AT[(j + 1) * SD + lane];
            a0 += w0 * xs[bl][0][j];
            c0 += w0 * xs[bl][1][j];
            a1 += w1 * xs[bl][0][j + 1];
            c1 += w1 * xs[bl][1][j + 1];
        }
        #pragma unroll
        for (int o = 0; o < OD; o += 2) {
            float w0 = KT[o * SD + lane];
            float w1 = KT[(o + 1) * SD + lane];
            a0 += w0 * zs[bl][0][o];
            c0 += w0 * zs[bl][1][o];
            a1 += w1 * zs[bl][0][o + 1];
            c1 += w1 * zs[bl][1][o + 1];
        }
        const float xa = a0 + a1;
        const float xc = c0 + c1;
        out[(b0 * TT + t) * SD + lane] = xa;
        out[(b1 * TT + t) * SD + lane] = xc;
        __syncthreads();

        xs[bl][0][lane] = xa;
        xs[bl][1][lane] = xc;
        if (t + 1 < TT) zs[bl][lane >> 4][lz] = zn;
        if (stage) {
            float4* d = (float4*)Wb[cur ^ 1];
            d[tid] = n0;
            if (tid < 128) d[256 + tid] = n1;
            cur ^= 1;
            tW = tn;
        }
        __syncthreads();
    }
}

// ---------------------------------------------------------------------------
extern "C" void kernel_launch(void* const* d_in, const int* in_sizes, int n_in,
                              void* d_out, int out_size) {
    const float* state0 = (const float*)d_in[0];  // (B, 32)
    const float* cov0   = (const float*)d_in[1];  // (B, 32, 32)
    const float* meas   = (const float*)d_in[2];  // (B, 64, 16)
    const float* F      = (const float*)d_in[3];  // (32, 32)
    const float* H      = (const float*)d_in[4];  // (16, 32)
    const float* Q      = (const float*)d_in[5];  // (32, 32)
    const float* R      = (const float*)d_in[6];  // (16, 16)
    float* out = (float*)d_out;                   // (B, 64, 32)
    (void)in_sizes; (void)n_in; (void)out_size;

    const int dyn = 2 * 16 * TT * OD * (int)sizeof(float);   // 128 KB: z + w/y
    cudaFuncSetAttribute(fused_kernel,
                         cudaFuncAttributeMaxDynamicSharedMemorySize, dyn);

    fused_kernel<<<NB / 16, 512, dyn>>>(state0, meas, out, F, H, Q, R, cov0);
    phase1_kernel<<<1, 256>>>(F, H, Q, R, cov0);        // no-op if special
    phase2_kernel<<<NB / 16, 256>>>(state0, meas, out); // no-op if special
}